// round 14
// baseline (speedup 1.0000x reference)
#include <cuda_runtime.h>
#include <cuda_fp16.h>

// ---------------------------------------------------------------------------
// MLPPredictor: score[e] = W3 @ relu(W2 @ relu(W1 @ [x[src];x[dst]] + b1) + b2) + b3
//
// W1 @ concat(xs,xd) = W1a@xs + W1b@xd -> node-level PQ GEMM (fp16 out),
// then per-edge gather + fused layer2 GEMM + layer3 dot.
//
// R12: BARRIER-FREE mainloops. Full weight tile (131 KB) + full A fragment
// buffer (67.6 KB) resident in smem (202 KB of the 227 KB carveout), one
// __syncthreads after the load phase, then 16 kt-halves of MMA with no
// synchronization at all — warps drift and self-overlap LDS vs HMMA.
// ---------------------------------------------------------------------------

#define D 256
#define NMAX 50000
#define AW 132                  // A frag block (16m x 16k = 128 words) + 4 pad
#define BW 66                   // B frag block (8n  x 16k =  64 words) + 2 pad
#define EA_WORDS (8 * 16 * AW)  // A buffer: 8 Mi x 16 Kk blocks = 16896 words
#define BCH_WORDS (32 * 2 * BW) // B chunk (32 k): 32 Ni x 2 Kk  = 4224 words

static __device__ __align__(16) __half g_PQh[(long long)NMAX * 512];  // 51.2 MB
static __device__ int   g_is64;
static __device__ __align__(16) __half g_W1h[256 * 512];
static __device__ __align__(16) __half g_W2h[256 * 256];

__device__ __forceinline__ unsigned f2h2(float lo, float hi) {
    __half2 h = __floats2half2_rn(lo, hi);
    return *reinterpret_cast<unsigned*>(&h);
}
__device__ __forceinline__ float2 h2f(unsigned u) {
    return __half22float2(*reinterpret_cast<__half2*>(&u));
}

__device__ __forceinline__ void mma16(float* d, const unsigned* a, const unsigned* b) {
    asm volatile(
        "mma.sync.aligned.m16n8k16.row.col.f32.f16.f16.f32 "
        "{%0,%1,%2,%3},{%4,%5,%6,%7},{%8,%9},{%0,%1,%2,%3};\n"
        : "+f"(d[0]), "+f"(d[1]), "+f"(d[2]), "+f"(d[3])
        : "r"(a[0]), "r"(a[1]), "r"(a[2]), "r"(a[3]), "r"(b[0]), "r"(b[1]));
}

// A-fragment reader: swizzled LDS.128 address (conflict-free; matches writers)
__device__ __forceinline__ unsigned a_rd_off(int lane) {
    return (unsigned)((lane * 4) ^ (((lane >> 3) & 3) << 2));
}

// ---------------------------------------------------------------------------
// prep: weight fp32->fp16 conversion (blocks 0..191) + idx dtype detect (192).
// ---------------------------------------------------------------------------
__global__ void prep(const float* __restrict__ W1, const float* __restrict__ W2,
                     const int* __restrict__ p, int E) {
    if (blockIdx.x < 192) {
        int idx = blockIdx.x * blockDim.x + threadIdx.x;
        if (idx < 32768) {
            float4 v = ((const float4*)W1)[idx];
            ((__half2*)g_W1h)[idx * 2]     = __floats2half2_rn(v.x, v.y);
            ((__half2*)g_W1h)[idx * 2 + 1] = __floats2half2_rn(v.z, v.w);
        } else if (idx < 49152) {
            int j = idx - 32768;
            float4 v = ((const float4*)W2)[j];
            ((__half2*)g_W2h)[j * 2]     = __floats2half2_rn(v.x, v.y);
            ((__half2*)g_W2h)[j * 2 + 1] = __floats2half2_rn(v.z, v.w);
        }
    } else {
        __shared__ int ok;
        if (threadIdx.x == 0) ok = 1;
        __syncthreads();
        int n = E < 1024 ? E : 1024;
        int bad = 0;
        for (int i = threadIdx.x; i < n; i += blockDim.x)
            if (p[2 * i + 1] != 0) bad = 1;
        if (bad) atomicAnd(&ok, 0);
        __syncthreads();
        if (threadIdx.x == 0) g_is64 = ok;
    }
}

// ---------------------------------------------------------------------------
// Kernel 1: g_PQh[i, n0+c] = fp16( sum_k x[i,k] * W1[c, n0+k] )
// CTA 128x256, 16 warps, warp 64x32. Full A + full B in smem, one sync,
// barrier-free mainloop.
// ---------------------------------------------------------------------------
__global__ __launch_bounds__(512) void node_gemm(const float* __restrict__ x,
                                                 int n_nodes) {
    extern __shared__ unsigned sm[];
    unsigned* Af = sm;               // [EA_WORDS]
    unsigned* Bf = sm + EA_WORDS;    // [8][BCH_WORDS]

    const int tid = threadIdx.x, lane = tid & 31, warp = tid >> 5;
    const int wm = warp >> 3, wn = warp & 7;
    const int g = lane >> 2, tg = lane & 3;
    const int m0 = blockIdx.x * 128, n0 = blockIdx.y * 256;

    // ---- full A load into fragment layout (swizzled) ----
    {
        const int r = tid >> 2, l4 = tid & 3;
        const int Mi = r >> 4, gg = (r & 15) & 7, hi = (r & 15) >> 3;
        const int swz = (gg >> 1) & 3;
        unsigned* fragp = Af + Mi * 16 * AW + gg * 16 + hi;
        int gr = m0 + r; if (gr >= n_nodes) gr = n_nodes - 1;
        const float4* X4 = (const float4*)(x + (long long)gr * D);
#pragma unroll
        for (int i = 0; i < 8; i++) {
            int c8 = i * 4 + l4;           // 8-float group index, 0..31
            float4 a0 = X4[c8 * 2], a1 = X4[c8 * 2 + 1];
            const int Kk = c8 >> 1, hc = (c8 & 1) * 2;
            unsigned* basep = fragp + Kk * AW;
            basep[((0 ^ swz) << 2) + hc] = f2h2(a0.x, a0.y);
            basep[((1 ^ swz) << 2) + hc] = f2h2(a0.z, a0.w);
            basep[((2 ^ swz) << 2) + hc] = f2h2(a1.x, a1.y);
            basep[((3 ^ swz) << 2) + hc] = f2h2(a1.z, a1.w);
        }
    }
    // ---- full B load: 8 chunks of W1 half ----
    {
        const int row = tid >> 1, hB = tid & 1;
        const int Ni = row >> 3, gb = row & 7;
        const __half* Brow = g_W1h + (long long)row * 512 + n0 + hB * 16;
#pragma unroll
        for (int ck = 0; ck < 8; ck++) {
            const uint4* p = (const uint4*)(Brow + ck * 32);
            uint4 w0 = p[0], w1 = p[1];
            unsigned* q0 = Bf + ck * BCH_WORDS + (Ni * 2 + (hB * 2 >> 1)) * BW + gb * 8 + ((hB * 2) & 1);
            q0[0] = w0.x; q0[2] = w0.y; q0[4] = w0.z; q0[6] = w0.w;
            unsigned* q1 = Bf + ck * BCH_WORDS + (Ni * 2 + ((hB * 2 + 1) >> 1)) * BW + gb * 8 + ((hB * 2 + 1) & 1);
            q1[0] = w1.x; q1[2] = w1.y; q1[4] = w1.z; q1[6] = w1.w;
        }
    }
    __syncthreads();

    float acc[4][4][4];
#pragma unroll
    for (int a = 0; a < 4; a++)
#pragma unroll
        for (int b = 0; b < 4; b++)
#pragma unroll
            for (int c = 0; c < 4; c++) acc[a][b][c] = 0.f;

    const unsigned aoff = a_rd_off(lane);
    const unsigned* Awarp = Af + (wm * 4) * 16 * AW + aoff;
#pragma unroll 2
    for (int kt = 0; kt < 8; ++kt) {
        const unsigned* Bc = Bf + kt * BCH_WORDS;
#pragma unroll
        for (int h = 0; h < 2; ++h) {
            const int Kkg = kt * 2 + h;
            uint4 af[4]; uint2 bf[4];
#pragma unroll
            for (int mi = 0; mi < 4; ++mi)
                af[mi] = *(const uint4*)(Awarp + (mi * 16 + Kkg) * AW);
#pragma unroll
            for (int ni = 0; ni < 4; ++ni)
                bf[ni] = *(const uint2*)(Bc + ((wn * 4 + ni) * 2 + h) * BW + lane * 2);
#pragma unroll
            for (int mi = 0; mi < 4; ++mi)
#pragma unroll
                for (int ni = 0; ni < 4; ++ni)
                    mma16(acc[mi][ni], (const unsigned*)&af[mi], (const unsigned*)&bf[ni]);
        }
    }

#pragma unroll
    for (int mi = 0; mi < 4; ++mi) {
        int r0 = m0 + wm * 64 + mi * 16 + g;
        int r1 = r0 + 8;
#pragma unroll
        for (int ni = 0; ni < 4; ++ni) {
            int c = n0 + wn * 32 + ni * 8 + tg * 2;
            if (r0 < n_nodes)
                *(unsigned*)(g_PQh + (long long)r0 * 512 + c) = f2h2(acc[mi][ni][0], acc[mi][ni][1]);
            if (r1 < n_nodes)
                *(unsigned*)(g_PQh + (long long)r1 * 512 + c) = f2h2(acc[mi][ni][2], acc[mi][ni][3]);
        }
    }
}

// ---------------------------------------------------------------------------
// Kernel 3: 128 edges/CTA, 512 threads, warp 64x32. Gather + full-W2 load
// (interleaved for latency overlap), one sync, barrier-free MMA mainloop,
// fused relu(+b2)*w3 + b3 epilogue.
// ---------------------------------------------------------------------------
__global__ __launch_bounds__(512) void edge_mlp(const void* __restrict__ srcv,
                                                const void* __restrict__ dstv,
                                                const float* __restrict__ b1,
                                                const float* __restrict__ b2,
                                                const float* __restrict__ W3,
                                                const float* __restrict__ b3,
                                                float* __restrict__ out, int E) {
    extern __shared__ unsigned sm[];
    unsigned* Af = sm;                      // [EA_WORDS]
    unsigned* Bf = sm + EA_WORDS;           // [8][BCH_WORDS]
    float* b2s   = (float*)(Bf + 8 * BCH_WORDS);  // 256
    float* w3s   = b2s + 256;                     // 256
    float* b1s   = w3s + 256;                     // 256
    float* score = b1s + 256;                     // 128

    const int tid = threadIdx.x, lane = tid & 31, warp = tid >> 5;
    const int wm = warp >> 3, wn = warp & 7;
    const int g = lane >> 2, tg = lane & 3;
    const int e0 = blockIdx.x * 128;
    const int is64 = g_is64;

    if (tid < 256) {
        b2s[tid] = b2[tid];
        w3s[tid] = W3[tid];
        b1s[tid] = b1[tid];
    }
    if (tid < 128) score[tid] = b3[0];
    __syncthreads();   // b1s needed by the gather below

    // ---- gather + layer1 and full-W2 load, interleaved ----
    {
        const int r = tid >> 2, l4 = tid & 3;
        const int Mi = r >> 4, gg = (r & 15) & 7, hi = (r & 15) >> 3;
        const int swz = (gg >> 1) & 3;
        unsigned* fragp = Af + Mi * 16 * AW + gg * 16 + hi;
        int e = e0 + r;
        if (e >= E) e = 0;   // garbage rows computed, never stored
        long long s, d;
        if (is64) { s = ((const long long*)srcv)[e]; d = ((const long long*)dstv)[e]; }
        else      { s = ((const int*)srcv)[e];       d = ((const int*)dstv)[e]; }
        const uint4* P8 = (const uint4*)(g_PQh + s * 512);
        const uint4* Q8 = (const uint4*)(g_PQh + d * 512 + 256);

        const int rowB = tid >> 1, hB = tid & 1;
        const int NiB = rowB >> 3, gB = rowB & 7;
        const __half* Brow = g_W2h + (long long)rowB * 256 + hB * 16;

#pragma unroll
        for (int i = 0; i < 8; i++) {
            // W2 chunk i (2 x LDG.128)
            const uint4* wp = (const uint4*)(Brow + i * 32);
            uint4 w0 = wp[0], w1 = wp[1];
            // gather step i (2 x LDG.128)
            int c8 = i * 4 + l4;
            uint4 pu = P8[c8], qu = Q8[c8];
            // W2 chunk i -> smem
            unsigned* q0 = Bf + i * BCH_WORDS + (NiB * 2 + hB) * BW + gB * 8;
            q0[0] = w0.x; q0[2] = w0.y; q0[4] = w0.z; q0[6] = w0.w;
            q0[1] = w1.x; q0[3] = w1.y; q0[5] = w1.z; q0[7] = w1.w;
            // layer-1 compute + fragment store
            const float* bb = b1s + c8 * 8;
            float v[8];
            float2 a, b;
            a = h2f(pu.x); b = h2f(qu.x);
            v[0] = fmaxf(a.x + b.x + bb[0], 0.f); v[1] = fmaxf(a.y + b.y + bb[1], 0.f);
            a = h2f(pu.y); b = h2f(qu.y);
            v[2] = fmaxf(a.x + b.x + bb[2], 0.f); v[3] = fmaxf(a.y + b.y + bb[3], 0.f);
            a = h2f(pu.z); b = h2f(qu.z);
            v[4] = fmaxf(a.x + b.x + bb[4], 0.f); v[5] = fmaxf(a.y + b.y + bb[5], 0.f);
            a = h2f(pu.w); b = h2f(qu.w);
            v[6] = fmaxf(a.x + b.x + bb[6], 0.f); v[7] = fmaxf(a.y + b.y + bb[7], 0.f);
            const int Kk = c8 >> 1, hc = (c8 & 1) * 2;
            unsigned* basep = fragp + Kk * AW;
#pragma unroll
            for (int t = 0; t < 4; t++)
                basep[((t ^ swz) << 2) + hc] = f2h2(v[2 * t], v[2 * t + 1]);
        }
    }
    __syncthreads();

    float acc[4][4][4];
#pragma unroll
    for (int a = 0; a < 4; a++)
#pragma unroll
        for (int b = 0; b < 4; b++)
#pragma unroll
            for (int c = 0; c < 4; c++) acc[a][b][c] = 0.f;

    const unsigned aoff = a_rd_off(lane);
    const unsigned* Awarp = Af + (wm * 4) * 16 * AW + aoff;
#pragma unroll 2
    for (int kt = 0; kt < 8; ++kt) {
        const unsigned* Bc = Bf + kt * BCH_WORDS;
#pragma unroll
        for (int h = 0; h < 2; ++h) {
            const int Kkg = kt * 2 + h;
            uint4 af[4]; uint2 bf[4];
#pragma unroll
            for (int mi = 0; mi < 4; ++mi)
                af[mi] = *(const uint4*)(Awarp + (mi * 16 + Kkg) * AW);
#pragma unroll
            for (int ni = 0; ni < 4; ++ni)
                bf[ni] = *(const uint2*)(Bc + ((wn * 4 + ni) * 2 + h) * BW + lane * 2);
#pragma unroll
            for (int mi = 0; mi < 4; ++mi)
#pragma unroll
                for (int ni = 0; ni < 4; ++ni)
                    mma16(acc[mi][ni], (const unsigned*)&af[mi], (const unsigned*)&bf[ni]);
        }
    }

    // ---- fused layer-2 bias/relu + layer-3 dot reduction ----
#pragma unroll
    for (int mi = 0; mi < 4; ++mi) {
        float rs0 = 0.f, rs1 = 0.f;
#pragma unroll
        for (int ni = 0; ni < 4; ++ni) {
            int n = wn * 32 + ni * 8 + tg * 2;
            float w0 = w3s[n], w1 = w3s[n + 1];
            float c0 = b2s[n], c1 = b2s[n + 1];
            rs0 += fmaxf(acc[mi][ni][0] + c0, 0.f) * w0 + fmaxf(acc[mi][ni][1] + c1, 0.f) * w1;
            rs1 += fmaxf(acc[mi][ni][2] + c0, 0.f) * w0 + fmaxf(acc[mi][ni][3] + c1, 0.f) * w1;
        }
        rs0 += __shfl_xor_sync(0xffffffffu, rs0, 1);
        rs0 += __shfl_xor_sync(0xffffffffu, rs0, 2);
        rs1 += __shfl_xor_sync(0xffffffffu, rs1, 1);
        rs1 += __shfl_xor_sync(0xffffffffu, rs1, 2);
        if (tg == 0) {
            atomicAdd(&score[wm * 64 + mi * 16 + g], rs0);
            atomicAdd(&score[wm * 64 + mi * 16 + g + 8], rs1);
        }
    }
    __syncthreads();

    if (tid < 128) {
        int e = e0 + tid;
        if (e < E) out[e] = score[tid];
    }
}

// ---------------------------------------------------------------------------
// Launch
// ---------------------------------------------------------------------------
extern "C" void kernel_launch(void* const* d_in, const int* in_sizes, int n_in,
                              void* d_out, int out_size) {
    const float* x  = (const float*)d_in[0];
    const void*  sv = d_in[1];
    const void*  dv = d_in[2];
    const float* W1 = (const float*)d_in[3];
    const float* b1 = (const float*)d_in[4];
    const float* W2 = (const float*)d_in[5];
    const float* b2 = (const float*)d_in[6];
    const float* W3 = (const float*)d_in[7];
    const float* b3 = (const float*)d_in[8];
    float* out = (float*)d_out;

    const int n_nodes = in_sizes[0] / D;
    const int E       = in_sizes[1];

    const int SM_NODE = (EA_WORDS + 8 * BCH_WORDS) * 4;          // 202752 B
    const int SM_EDGE = (EA_WORDS + 8 * BCH_WORDS + 896) * 4;    // 206336 B
    cudaFuncSetAttribute(node_gemm, cudaFuncAttributeMaxDynamicSharedMemorySize, SM_NODE);
    cudaFuncSetAttribute(edge_mlp,  cudaFuncAttributeMaxDynamicSharedMemorySize, SM_EDGE);

    prep<<<193, 256>>>(W1, W2, (const int*)sv, E);

    dim3 g1((n_nodes + 127) / 128, 2);
    node_gemm<<<g1, 512, SM_NODE>>>(x, n_nodes);

    int g2 = (E + 127) / 128;
    edge_mlp<<<g2, 512, SM_EDGE>>>(sv, dv, b1, b2, W3, b3, out, E);
}